// round 10
// baseline (speedup 1.0000x reference)
#include <cuda_runtime.h>
#include <math.h>
#include <stdint.h>

#define C 256
#define HW 65536
#define BMPIX 128          // pixels per CTA
#define NCHUNK 8           // K chunks of 32

__device__ float g_X[C * C];
__device__ float g_XT[C * C];
__device__ float g_coef[C * 3];
__device__ float g_sel[C];
// B pre-packed for mma fragments:
// float4[c][ks][n][kb] = { hi(k), lo(k), hi(k+4), lo(k+4) },  k = c*32+ks*8+kb
__device__ float4 g_bpack[NCHUNK * 4 * 256 * 4];

__device__ __forceinline__ float tf32r(float x) {
    uint32_t u;
    asm("cvt.rna.tf32.f32 %0, %1;" : "=r"(u) : "f"(x));
    return __uint_as_float(u);
}
__device__ __forceinline__ uint32_t smem_u32(const void* p) {
    uint32_t a;
    asm("{ .reg .u64 t; cvta.to.shared.u64 t, %1; cvt.u32.u64 %0, t; }" : "=r"(a) : "l"(p));
    return a;
}
__device__ __forceinline__ void mma8(float* d, const uint32_t* a,
                                     uint32_t b0, uint32_t b1) {
    asm("mma.sync.aligned.m16n8k8.row.col.f32.tf32.tf32.f32 "
        "{%0,%1,%2,%3}, {%4,%5,%6,%7}, {%8,%9}, {%0,%1,%2,%3};"
        : "+f"(d[0]), "+f"(d[1]), "+f"(d[2]), "+f"(d[3])
        : "r"(a[0]), "r"(a[1]), "r"(a[2]), "r"(a[3]), "r"(b0), "r"(b1));
}
#define CP_ASYNC16(dst, src) \
    asm volatile("cp.async.ca.shared.global [%0], [%1], 16;" :: "r"(dst), "l"(src) : "memory")
#define CP_COMMIT() asm volatile("cp.async.commit_group;" ::: "memory")
#define CP_WAIT1()  asm volatile("cp.async.wait_group 1;" ::: "memory")

// ---------------------------------------------------------------------------
__global__ void pool_kernel(const float* __restrict__ sup_x,
                            const float* __restrict__ sup_y) {
    const int bc = blockIdx.x, tid = threadIdx.x;
    const int ph = tid >> 4, pw = tid & 15;
    const float* src = (bc < C) ? (sup_x + (size_t)bc * HW) : sup_y;
    const float* base = src + ph * 16 * 256 + pw * 16;
    float s = 0.f;
#pragma unroll
    for (int r = 0; r < 16; ++r) {
        const float4* row = (const float4*)(base + r * 256);
        float4 a = row[0], b = row[1], c = row[2], d = row[3];
        s += (a.x + a.y + a.z + a.w) + (b.x + b.y + b.z + b.w)
           + (c.x + c.y + c.z + c.w) + (d.x + d.y + d.z + d.w);
    }
    s *= (1.0f / 256.0f);
    if (bc < C) { g_X[bc * C + tid] = s; g_XT[tid * C + bc] = s; }
    else        { g_sel[tid] = (s > 0.5f) ? 1.0f : 0.0f; }
}

__global__ void w1_kernel(const float* __restrict__ cal) {
    __shared__ float Xi[C], red[C];
    const int i = blockIdx.x, j = threadIdx.x;
    Xi[j] = g_X[i * C + j];
    __syncthreads();
    float dot = 0.f;
#pragma unroll 8
    for (int p = 0; p < C; ++p) dot += Xi[p] * g_XT[p * C + j];
    red[j] = dot; __syncthreads();
    for (int s = 128; s > 0; s >>= 1) { if (j < s) red[j] = fmaxf(red[j], red[j + s]); __syncthreads(); }
    const float mx = red[0]; __syncthreads();
    red[j] = expf(dot - mx); __syncthreads();
    for (int s = 128; s > 0; s >>= 1) { if (j < s) red[j] += red[j + s]; __syncthreads(); }
    const float denom = red[0];
    if (j >= i - 1 && j <= i + 1)
        g_coef[i * 3 + (j - i + 1)] = (1.0f + 0.2f * expf(dot - mx) / denom) * cal[i * C + j];
    if (i == 0 && j == 0)         g_coef[0] = 0.f;
    if (i == C - 1 && j == C - 1) g_coef[(C - 1) * 3 + 2] = 0.f;
}

// proto values -> packed tf32 hi/lo fragment layout
__global__ void proto_kernel() {
    __shared__ float red[C];
    const int p = blockIdx.x, i = threadIdx.x;   // p = proto, i = channel
    const float c0 = g_coef[i * 3], c1 = g_coef[i * 3 + 1], c2 = g_coef[i * 3 + 2];
    const float xm1 = (i > 0) ? g_XT[p * C + i - 1] : 0.f;
    const float x0 = g_XT[p * C + i];
    const float xp1 = (i < C - 1) ? g_XT[p * C + i + 1] : 0.f;
    const float xn = c0 * xm1 + c1 * x0 + c2 * xp1;
    red[i] = xn * xn; __syncthreads();
    for (int s = 128; s > 0; s >>= 1) { if (i < s) red[i] += red[i + s]; __syncthreads(); }
    const float v = xn * (20.0f / fmaxf(sqrtf(red[0]), 1e-4f));
    const float h = tf32r(v);
    const float l = tf32r(v - h);
    const int c = i >> 5, ks = (i >> 3) & 3, klow = i & 7;
    const int kb = klow & 3, h4 = klow >> 2;
    float* dst = (float*)&g_bpack[c * 4096 + ((ks * 256 + p) << 2) + kb];
    dst[h4 * 2]     = h;
    dst[h4 * 2 + 1] = l;
}

// ---------------------------------------------------------------------------
// mma.sync tf32 3-term GEMM (M=128/block, N=256, K=256) + fused epilogue.
// Double-buffered cp.async B staging; whole-chunk A prefetch into registers.
// ---------------------------------------------------------------------------
#define SM_SEL  131072
#define SM_CSE  132096
#define SM_CSD  132608
#define SM_CBV  133120
#define SM_CBN  133632
#define SMEM_BYTES 134144

__global__ __launch_bounds__(256, 1) void gemm_mma_kernel(
    const float* __restrict__ qry, float* __restrict__ out) {
    extern __shared__ __align__(16) char sm[];
    float4* bsm = (float4*)sm;                       // 2 x 64KB: [ks][n][kb]
    float* sel_s = (float*)(sm + SM_SEL);
    const uint32_t smb = smem_u32(sm);

    const int tid = threadIdx.x, wid = tid >> 5, lane = tid & 31;
    const int lq = lane >> 2, lk = lane & 3;
    const int widM = wid & 3, widN = wid >> 2;
    const int m0 = blockIdx.x * BMPIX;

    sel_s[tid] = g_sel[tid];

    float acc[2][16][4];
#pragma unroll
    for (int mt = 0; mt < 2; ++mt)
#pragma unroll
        for (int nt = 0; nt < 16; ++nt)
#pragma unroll
            for (int q = 0; q < 4; ++q) acc[mt][nt][q] = 0.f;
    float nrm[2][2] = {{0.f, 0.f}, {0.f, 0.f}};

    const float* qbase = qry + m0 + widM * 32 + lq;
    const uint32_t cpdst = smb + tid * 16;

    // prologue: stage chunks 0 and 1
#pragma unroll
    for (int pc = 0; pc < 2; ++pc) {
        const float4* src = g_bpack + pc * 4096 + tid;
        const uint32_t d0 = cpdst + pc * 65536;
#pragma unroll
        for (int t = 0; t < 16; ++t)
            CP_ASYNC16(d0 + t * 4096, (const void*)(src + t * 256));
        CP_COMMIT();
    }

    for (int c = 0; c < NCHUNK; ++c) {
        const int s = c & 1;
        // ---- batch-load the whole chunk's raw A (32 floats) ----
        float av[4][2][4];
#pragma unroll
        for (int ks = 0; ks < 4; ++ks) {
            const float* q0 = qbase + (size_t)(c * 32 + ks * 8 + lk) * HW;
            const float* q4 = q0 + (size_t)4 * HW;
#pragma unroll
            for (int mt = 0; mt < 2; ++mt) {
                av[ks][mt][0] = q0[mt * 16];
                av[ks][mt][1] = q0[mt * 16 + 8];
                av[ks][mt][2] = q4[mt * 16];
                av[ks][mt][3] = q4[mt * 16 + 8];
            }
        }
        CP_WAIT1();
        __syncthreads();

#pragma unroll
        for (int ks = 0; ks < 4; ++ks) {
            uint32_t ah[2][4], al[2][4];
#pragma unroll
            for (int mt = 0; mt < 2; ++mt) {
                float v0 = av[ks][mt][0], v1 = av[ks][mt][1];
                float v2 = av[ks][mt][2], v3 = av[ks][mt][3];
                nrm[mt][0] += v0 * v0 + v2 * v2;
                nrm[mt][1] += v1 * v1 + v3 * v3;
                float h0 = tf32r(v0), h1 = tf32r(v1), h2 = tf32r(v2), h3 = tf32r(v3);
                ah[mt][0] = __float_as_uint(h0);
                ah[mt][1] = __float_as_uint(h1);
                ah[mt][2] = __float_as_uint(h2);
                ah[mt][3] = __float_as_uint(h3);
                al[mt][0] = __float_as_uint(tf32r(v0 - h0));
                al[mt][1] = __float_as_uint(tf32r(v1 - h1));
                al[mt][2] = __float_as_uint(tf32r(v2 - h2));
                al[mt][3] = __float_as_uint(tf32r(v3 - h3));
            }
            const float4* bp = bsm + s * 4096 + ks * 1024 + widN * 512 + lq * 4 + lk;
#pragma unroll
            for (int nt = 0; nt < 16; ++nt) {
                float4 b = bp[nt * 32];
                uint32_t bh0 = __float_as_uint(b.x), bl0 = __float_as_uint(b.y);
                uint32_t bh1 = __float_as_uint(b.z), bl1 = __float_as_uint(b.w);
                mma8(acc[0][nt], ah[0], bh0, bh1);
                mma8(acc[1][nt], ah[1], bh0, bh1);
                mma8(acc[0][nt], al[0], bh0, bh1);
                mma8(acc[1][nt], al[1], bh0, bh1);
                mma8(acc[0][nt], ah[0], bl0, bl1);
                mma8(acc[1][nt], ah[1], bl0, bl1);
            }
        }
        __syncthreads();
        // ---- stage chunk c+2 into the buffer we just finished reading ----
        if (c + 2 < NCHUNK) {
            const float4* src = g_bpack + (c + 2) * 4096 + tid;
            const uint32_t d0 = cpdst + s * 65536;
#pragma unroll
            for (int t = 0; t < 16; ++t)
                CP_ASYNC16(d0 + t * 4096, (const void*)(src + t * 256));
        }
        CP_COMMIT();
    }

    // ---- per-pixel inverse norms (4-lane reduce over lk group) ----
    float qs[2][2];
#pragma unroll
    for (int mt = 0; mt < 2; ++mt)
#pragma unroll
        for (int hi = 0; hi < 2; ++hi) {
            float nr = nrm[mt][hi];
            nr += __shfl_xor_sync(0xFFFFFFFFu, nr, 1);
            nr += __shfl_xor_sync(0xFFFFFFFFu, nr, 2);
            qs[mt][hi] = 1.0f / fmaxf(sqrtf(nr), 1e-4f);
        }

    // ---- fused masked softmax + weighted sum + argmax ----
    float* cse = (float*)(sm + SM_CSE);
    float* csd = (float*)(sm + SM_CSD);
    float* cbv = (float*)(sm + SM_CBV);
    int*   cbn = (int*)  (sm + SM_CBN);
    const int nbase = widN * 128 + lk * 2;

#pragma unroll
    for (int mt = 0; mt < 2; ++mt)
#pragma unroll
        for (int hi = 0; hi < 2; ++hi) {
            const float sc = qs[mt][hi];
            float se = 0.f, sd = 0.f, bv = -3.0e38f;
            int bn = 1 << 30;
#pragma unroll
            for (int nt = 0; nt < 16; ++nt)
#pragma unroll
                for (int c2 = 0; c2 < 2; ++c2) {
                    const int n = nbase + nt * 8 + c2;
                    float mv = (sel_s[n] > 0.5f)
                             ? acc[mt][nt][hi * 2 + c2] * sc : -1.0e9f;
                    if (mv > bv) { bv = mv; bn = n; }
                    float e = __expf(mv);       // unshifted; mv <= 20
                    se += e;
                    sd += e * mv;
                }
#pragma unroll
            for (int off = 1; off <= 2; off <<= 1) {
                float ov = __shfl_xor_sync(0xFFFFFFFFu, bv, off);
                int   on = __shfl_xor_sync(0xFFFFFFFFu, bn, off);
                se += __shfl_xor_sync(0xFFFFFFFFu, se, off);
                sd += __shfl_xor_sync(0xFFFFFFFFu, sd, off);
                if (ov > bv || (ov == bv && on < bn)) { bv = ov; bn = on; }
            }
            const int pix = widM * 32 + mt * 16 + hi * 8 + lq;
            if (widN == 1 && lk == 0) {
                cse[pix] = se; csd[pix] = sd; cbv[pix] = bv; cbn[pix] = bn;
            }
            nrm[mt][hi] = se;  qs[mt][hi] = sd;
            acc[mt][0][hi] = bv; acc[mt][1][hi] = __int_as_float(bn);
        }
    __syncthreads();
    if (widN == 0 && lk == 0) {
#pragma unroll
        for (int mt = 0; mt < 2; ++mt)
#pragma unroll
            for (int hi = 0; hi < 2; ++hi) {
                const int pix = widM * 32 + mt * 16 + hi * 8 + lq;
                float se = nrm[mt][hi] + cse[pix];
                float sd = qs[mt][hi] + csd[pix];
                float bv = acc[mt][0][hi];
                int bn = __float_as_int(acc[mt][1][hi]);
                if (cbv[pix] > bv) { bv = cbv[pix]; bn = cbn[pix]; }
                out[m0 + pix]      = sd / se;
                out[HW + m0 + pix] = (float)bn;
            }
    }
}

// ---------------------------------------------------------------------------
extern "C" void kernel_launch(void* const* d_in, const int* in_sizes, int n_in,
                              void* d_out, int out_size) {
    const float* qry   = (const float*)d_in[0];
    const float* sup_x = (const float*)d_in[1];
    const float* sup_y = (const float*)d_in[2];
    const float* cal   = (const float*)d_in[4];
    float* out = (float*)d_out;

    cudaFuncSetAttribute(gemm_mma_kernel,
                         cudaFuncAttributeMaxDynamicSharedMemorySize, SMEM_BYTES);

    pool_kernel<<<C + 1, 256>>>(sup_x, sup_y);
    w1_kernel<<<C, 256>>>(cal);
    proto_kernel<<<C, 256>>>();
    gemm_mma_kernel<<<HW / BMPIX, 256, SMEM_BYTES>>>(qry, out);
}